// round 13
// baseline (speedup 1.0000x reference)
#include <cuda_runtime.h>
#include <cuda_fp16.h>
#include <math.h>

#define Bb 64
#define Cc 64
#define Dd 512
#define Oo 256
#define NREG 8
#define Gg 8
#define Mrows (Bb*Cc)   // 4096

// ---------------- Scratch (device globals) ----------------
__device__ __half g_ah [Mrows*Dd];      // x @ W1a (fp16)
__device__ __half g_bph[Mrows*Dd];      // x @ W1b + b1 (fp16)
__device__ __half g_y1h[Mrows*Dd];      // x @ Wg1 (fp16)
__device__ __half g_xh [Mrows*Dd];      // x  (fp16)
__device__ __half g_m2h[Mrows*Dd];      // m2 = adj @ x1 (fp16)
__device__ __half g_wbt [3*Dd*Dd];      // [W1a^T; W1b^T; Wg1^T]  [n][k] fp16
__device__ __half g_wg2t[Oo*Dd];        // Wg2^T fp16

// ---------------- async / ldmatrix helpers ----------------
__device__ __forceinline__ void cpasync16(void* smem, const void* g)
{
    unsigned sa = (unsigned)__cvta_generic_to_shared(smem);
    asm volatile("cp.async.cg.shared.global [%0], [%1], 16;" :: "r"(sa), "l"(g));
}
__device__ __forceinline__ void cp_commit() { asm volatile("cp.async.commit_group;"); }
template<int N> __device__ __forceinline__ void cp_wait()
{
    asm volatile("cp.async.wait_group %0;" :: "n"(N));
}
__device__ __forceinline__ void ldmx4(unsigned& r0, unsigned& r1, unsigned& r2,
                                      unsigned& r3, const void* p)
{
    unsigned a = (unsigned)__cvta_generic_to_shared(p);
    asm volatile("ldmatrix.sync.aligned.m8n8.x4.shared.b16 {%0,%1,%2,%3}, [%4];"
        : "=r"(r0), "=r"(r1), "=r"(r2), "=r"(r3) : "r"(a));
}
__device__ __forceinline__ void mma_f16(float c[4],
    unsigned a0, unsigned a1, unsigned a2, unsigned a3,
    unsigned b0, unsigned b1)
{
    asm volatile(
        "mma.sync.aligned.m16n8k16.row.col.f32.f16.f16.f32 "
        "{%0,%1,%2,%3}, {%4,%5,%6,%7}, {%8,%9}, {%0,%1,%2,%3};\n"
        : "+f"(c[0]), "+f"(c[1]), "+f"(c[2]), "+f"(c[3])
        : "r"(a0), "r"(a1), "r"(a2), "r"(a3), "r"(b0), "r"(b1));
}
__device__ __forceinline__ unsigned pack_half2(float a, float b)
{
    __half2 h = __halves2half2(__float2half_rn(a), __float2half_rn(b));
    return *(unsigned*)&h;
}

// ---------------- Combined prep kernel ----------------
__device__ __forceinline__ void transpose_tile(
    const float* __restrict__ src, __half* __restrict__ dst,
    int K, int N, int tn, int tk)
{
    __shared__ float tile[32][36];
    const int tid = threadIdx.x;
    const int k0 = tk * 32, n0 = tn * 32;
    // Vectorized load: 32 rows x 8 float4 = 256 threads, 1 float4 each
    {
        int row = tid >> 3, c4 = tid & 7;
        float4 v = *(const float4*)(src + (size_t)(k0 + row) * N + n0 + c4 * 4);
        tile[row][c4 * 4]     = v.x;
        tile[row][c4 * 4 + 1] = v.y;
        tile[row][c4 * 4 + 2] = v.z;
        tile[row][c4 * 4 + 3] = v.w;
    }
    __syncthreads();
    const int nr = tid >> 4;
    const int kp = tid & 15;
    #pragma unroll
    for (int i = 0; i < 2; i++) {
        int n = n0 + nr + 16 * i;
        float v0 = tile[2 * kp    ][nr + 16 * i];
        float v1 = tile[2 * kp + 1][nr + 16 * i];
        *(unsigned*)&dst[(size_t)n * K + k0 + 2 * kp] = pack_half2(v0, v1);
    }
}

__global__ __launch_bounds__(256)
void prep_kernel(const float* __restrict__ x, const float* __restrict__ W1,
                 const float* __restrict__ Wg1, const float* __restrict__ Wg2,
                 __half* __restrict__ xh,
                 __half* __restrict__ wbt, __half* __restrict__ wg2t)
{
    int b = blockIdx.x;
    if (b < 256) {
        transpose_tile(W1, wbt, Dd, Dd, b & 15, b >> 4);
    } else if (b < 512) {
        b -= 256;
        transpose_tile(W1 + (size_t)Dd * Dd, wbt + (size_t)Dd * Dd, Dd, Dd, b & 15, b >> 4);
    } else if (b < 768) {
        b -= 512;
        transpose_tile(Wg1, wbt + 2 * (size_t)Dd * Dd, Dd, Dd, b & 15, b >> 4);
    } else if (b < 896) {
        b -= 768;
        transpose_tile(Wg2, wg2t, Dd, Oo, b & 7, b >> 3);
    } else {
        b -= 896;   // 256 blocks: x -> fp16
        const float4* src = (const float4*)x;
        uint2* dh = (uint2*)xh;
        const int n4 = Mrows * Dd / 4;
        for (int i = b * 256 + threadIdx.x; i < n4; i += 256 * 256) {
            float4 v = src[i];
            dh[i] = make_uint2(pack_half2(v.x, v.y), pack_half2(v.z, v.w));
        }
    }
}

// ---------------- fp16 tensor-core GEMM ----------------
// MODE 1: fp32 out, leaky(z + bias)
// MODE 5: triple fp16 route: col<512 -> Ch raw; 512..1023 -> C2h + bias; >=1024 -> C3h raw
template<int MODE, int BM, int BN>
__global__ __launch_bounds__(256, 2)
void mgemm_kernel(const __half* __restrict__ A, const __half* __restrict__ Bt,
                  const float* __restrict__ bias,
                  float* __restrict__ C,
                  __half* __restrict__ Ch, __half* __restrict__ C2h,
                  __half* __restrict__ C3h, int N, int K)
{
    constexpr int BK = 32, LDT = 40, STAGES = 3;
    constexpr int WROWS = BM / 32;                  // warps along M
    constexpr int WCOLS = BN * WROWS / 8;           // warp tile N
    constexpr int NT = WCOLS / 8;
    constexpr int P  = (WCOLS / 16) ? WCOLS / 16 : 1;
    constexpr int A_SZ = BM * LDT;
    constexpr int B_SZ = BN * LDT;
    constexpr int STG  = A_SZ + B_SZ;
    constexpr int ACH  = BM / 64;                   // A 16B-chunks per thread
    constexpr int BCHUNKS = 4 * BN;                 // B 16B-chunks per stage
    extern __shared__ __half dsm[];

    const int tid  = threadIdx.x;
    const int wid  = tid >> 5;
    const int lane = tid & 31;
    const int wm   = wid % WROWS;
    const int wn   = wid / WROWS;
    const int row0 = blockIdx.y * BM;
    const int col0 = blockIdx.x * BN;
    const int g = lane >> 2;
    const int t = lane & 3;
    const int lq = lane >> 3, li = lane & 7;
    const int fr_off = (lq & 1) * 8 + li;
    const int fk_off = (lq >> 1) * 8;

    float acc[2][NT][4];
    #pragma unroll
    for (int mt = 0; mt < 2; mt++)
        #pragma unroll
        for (int nt = 0; nt < NT; nt++)
            #pragma unroll
            for (int q = 0; q < 4; q++) acc[mt][nt][q] = 0.f;

    auto load_stage = [&](int st, int kt) {
        __half* sA = dsm + st * STG;
        __half* sB = sA + A_SZ;
        #pragma unroll
        for (int i = 0; i < ACH; i++) {
            int id = tid * ACH + i;
            int r = id >> 2, c = (id & 3) * 8;
            cpasync16(sA + r * LDT + c, A + (size_t)(row0 + r) * K + kt + c);
        }
        if (tid < BCHUNKS) {
            int r = tid >> 2, c = (tid & 3) * 8;
            cpasync16(sB + r * LDT + c, Bt + (size_t)(col0 + r) * K + kt + c);
        }
    };

    const int nk = K / BK;
    load_stage(0, 0); cp_commit();
    load_stage(1, BK); cp_commit();

    for (int s = 0; s < nk; s++) {
        if (s + 2 < nk) { load_stage((s + 2) % STAGES, (s + 2) * BK); cp_commit(); cp_wait<2>(); }
        else if (s + 1 < nk) { cp_wait<1>(); }
        else { cp_wait<0>(); }
        __syncthreads();

        const int st = s % STAGES;
        __half* sA = dsm + st * STG;
        __half* sB = sA + A_SZ;

        #pragma unroll
        for (int kk = 0; kk < BK; kk += 16) {
            unsigned ah[2][4], bv[P][4];
            #pragma unroll
            for (int mt = 0; mt < 2; mt++) {
                const __half* pa = sA + (wm * 32 + mt * 16 + fr_off) * LDT + kk + fk_off;
                ldmx4(ah[mt][0], ah[mt][1], ah[mt][2], ah[mt][3], pa);
            }
            #pragma unroll
            for (int p = 0; p < P; p++) {
                const __half* pb = sB + (wn * WCOLS + p * 16 + fr_off) * LDT + kk + fk_off;
                ldmx4(bv[p][0], bv[p][1], bv[p][2], bv[p][3], pb);
            }
            #pragma unroll
            for (int mt = 0; mt < 2; mt++)
                #pragma unroll
                for (int nt = 0; nt < NT; nt++) {
                    const int p = nt >> 1, o = nt & 1;
                    mma_f16(acc[mt][nt], ah[mt][0], ah[mt][1], ah[mt][2], ah[mt][3],
                            bv[p][o], bv[p][2 + o]);
                }
        }
        __syncthreads();
    }

    #pragma unroll
    for (int mt = 0; mt < 2; mt++) {
        int rbase = row0 + wm * 32 + mt * 16;
        #pragma unroll
        for (int nt = 0; nt < NT; nt++) {
            int cb = col0 + wn * WCOLS + nt * 8 + 2 * t;
            #pragma unroll
            for (int h = 0; h < 2; h++) {
                int r = rbase + g + 8 * h;
                float v0 = acc[mt][nt][2*h];
                float v1 = acc[mt][nt][2*h + 1];
                if (MODE == 5) {
                    if (cb < Dd) {
                        *(unsigned*)&Ch[(size_t)r * Dd + cb] = pack_half2(v0, v1);
                    } else if (cb < 2 * Dd) {
                        int c2 = cb - Dd;
                        v0 += bias[c2]; v1 += bias[c2 + 1];
                        *(unsigned*)&C2h[(size_t)r * Dd + c2] = pack_half2(v0, v1);
                    } else {
                        int c3 = cb - 2 * Dd;
                        *(unsigned*)&C3h[(size_t)r * Dd + c3] = pack_half2(v0, v1);
                    }
                } else {
                    v0 += bias[cb]; v1 += bias[cb + 1];
                    v0 = (v0 >= 0.f) ? v0 : 0.2f * v0;
                    v1 = (v1 >= 0.f) ? v1 : 0.2f * v1;
                    *(float2*)(C + (size_t)r * N + cb) = make_float2(v0, v1);
                }
            }
        }
    }
}

// ---------------------------------------------------------------------------
// Fused attention + BOTH aggregations (unchanged from R12)
// ---------------------------------------------------------------------------
__global__ __launch_bounds__(256)
void attnagg2_kernel(const __half* __restrict__ ah, const __half* __restrict__ bph,
                     const float* __restrict__ W2, const float* __restrict__ b2,
                     const __half* __restrict__ y1h, const __half* __restrict__ xh,
                     const float* __restrict__ bg1, const int* __restrict__ ridx,
                     __half* __restrict__ m2h)
{
    __shared__ float sa[Gg][Dd];
    __shared__ float sb[Gg][Dd];
    __shared__ float sw2[Dd];
    __shared__ float ssc[Gg][Gg];
    __shared__ float ww[Gg * Gg];
    __shared__ int   ch[Gg];

    const int tid  = threadIdx.x;
    const int blk  = blockIdx.x;
    const int b    = blk >> 3;
    const int r    = blk & 7;

    if (tid < Gg) ch[tid] = ridx[r * Gg + tid];
    __syncthreads();

    #pragma unroll
    for (int u = 0; u < 2; u++) {
        int id = tid + 256 * u;
        int j = id >> 6, c8 = id & 63;
        size_t roff = (size_t)(b * Cc + ch[j]) * Dd;
        uint4 va = ((const uint4*)(ah  + roff))[c8];
        uint4 vb = ((const uint4*)(bph + roff))[c8];
        const unsigned* pa = &va.x;
        const unsigned* pb = &vb.x;
        #pragma unroll
        for (int q = 0; q < 4; q++) {
            float2 fa = __half22float2(*(__half2*)&pa[q]);
            float2 fb = __half22float2(*(__half2*)&pb[q]);
            sa[j][c8 * 8 + 2 * q]     = fa.x;
            sa[j][c8 * 8 + 2 * q + 1] = fa.y;
            sb[j][c8 * 8 + 2 * q]     = fb.x;
            sb[j][c8 * 8 + 2 * q + 1] = fb.y;
        }
    }
    if (tid < 128) ((float4*)sw2)[tid] = ((const float4*)W2)[tid];
    __syncthreads();

    const int wid  = tid >> 5;
    const int lane = tid & 31;
    {
        float accq[Gg];
        #pragma unroll
        for (int q = 0; q < Gg; q++) accq[q] = 0.f;
        for (int t = lane; t < Dd; t += 32) {
            float av = sa[wid][t];
            float wv = sw2[t];
            #pragma unroll
            for (int q = 0; q < Gg; q++) {
                float v = av + sb[q][t];
                v = fmaxf(v, 0.f);
                accq[q] = fmaf(v, wv, accq[q]);
            }
        }
        #pragma unroll
        for (int q = 0; q < Gg; q++) {
            #pragma unroll
            for (int off = 16; off > 0; off >>= 1)
                accq[q] += __shfl_xor_sync(0xffffffffu, accq[q], off);
        }
        if (lane == 0) {
            float bb2 = b2[0];
            #pragma unroll
            for (int q = 0; q < Gg; q++) ssc[wid][q] = accq[q] + bb2;
        }
    }
    __syncthreads();

    if (tid < Gg) {
        int i = tid;
        float mx = -1e30f;
        #pragma unroll
        for (int j = 0; j < Gg; j++)
            if (j != i) mx = fmaxf(mx, ssc[i][j]);
        float e[Gg]; float s = 0.f;
        #pragma unroll
        for (int j = 0; j < Gg; j++) {
            e[j] = (j == i) ? 0.f : __expf(ssc[i][j] - mx);
            s += e[j];
        }
        float inv = 1.f / s;
        #pragma unroll
        for (int j = 0; j < Gg; j++) ww[i * Gg + j] = e[j] * inv;
    }
    __syncthreads();

    #pragma unroll
    for (int u = 0; u < 2; u++) {
        int id = tid + 256 * u;
        int j = id >> 6, c8 = id & 63;
        size_t roff = (size_t)(b * Cc + ch[j]) * Dd;
        uint4 vy = ((const uint4*)(y1h + roff))[c8];
        const unsigned* py = &vy.x;
        #pragma unroll
        for (int q = 0; q < 4; q++) {
            float2 fy = __half22float2(*(__half2*)&py[q]);
            sa[j][c8 * 8 + 2 * q]     = fy.x;
            sa[j][c8 * 8 + 2 * q + 1] = fy.y;
        }
    }
    __syncthreads();

    #pragma unroll
    for (int u = 0; u < 4; u++) {
        int id = tid + 256 * u;
        int i = id >> 7, d4 = id & 127;
        float wi[Gg];
        #pragma unroll
        for (int j = 0; j < Gg; j++) wi[j] = ww[i * Gg + j];
        float a0 = 0.f, a1 = 0.f, a2 = 0.f, a3 = 0.f;
        #pragma unroll
        for (int j = 0; j < Gg; j++) {
            const float* yr = &sa[j][d4 * 4];
            a0 = fmaf(wi[j], yr[0], a0);
            a1 = fmaf(wi[j], yr[1], a1);
            a2 = fmaf(wi[j], yr[2], a2);
            a3 = fmaf(wi[j], yr[3], a3);
        }
        float4 bv = ((const float4*)bg1)[d4];
        uint2 xv = ((const uint2*)(xh + (size_t)(b * Cc + ch[i]) * Dd))[d4];
        float2 x01 = __half22float2(*(__half2*)&xv.x);
        float2 x23 = __half22float2(*(__half2*)&xv.y);
        float z0 = a0 + bv.x, z1 = a1 + bv.y, z2 = a2 + bv.z, z3 = a3 + bv.w;
        z0 = (z0 >= 0.f) ? z0 : 0.2f * z0;
        z1 = (z1 >= 0.f) ? z1 : 0.2f * z1;
        z2 = (z2 >= 0.f) ? z2 : 0.2f * z2;
        z3 = (z3 >= 0.f) ? z3 : 0.2f * z3;
        sb[i][d4 * 4    ] = 0.5f * z0 + 0.5f * x01.x;
        sb[i][d4 * 4 + 1] = 0.5f * z1 + 0.5f * x01.y;
        sb[i][d4 * 4 + 2] = 0.5f * z2 + 0.5f * x23.x;
        sb[i][d4 * 4 + 3] = 0.5f * z3 + 0.5f * x23.y;
    }
    __syncthreads();

    #pragma unroll
    for (int u = 0; u < 4; u++) {
        int id = tid + 256 * u;
        int i = id >> 7, d4 = id & 127;
        float wi[Gg];
        #pragma unroll
        for (int j = 0; j < Gg; j++) wi[j] = ww[i * Gg + j];
        float a0 = 0.f, a1 = 0.f, a2 = 0.f, a3 = 0.f;
        #pragma unroll
        for (int j = 0; j < Gg; j++) {
            const float* xr = &sb[j][d4 * 4];
            a0 = fmaf(wi[j], xr[0], a0);
            a1 = fmaf(wi[j], xr[1], a1);
            a2 = fmaf(wi[j], xr[2], a2);
            a3 = fmaf(wi[j], xr[3], a3);
        }
        size_t rowoff = (size_t)(b * Cc + ch[i]) * Dd;
        ((uint2*)(m2h + rowoff))[d4] = make_uint2(pack_half2(a0, a1), pack_half2(a2, a3));
    }
}

// ---------------------------------------------------------------------------
extern "C" void kernel_launch(void* const* d_in, const int* in_sizes, int n_in,
                              void* d_out, int out_size)
{
    const float* x    = (const float*)d_in[0];
    const float* W1   = (const float*)d_in[1];
    const float* b1   = (const float*)d_in[2];
    const float* W2   = (const float*)d_in[3];
    const float* b2   = (const float*)d_in[4];
    const float* Wg1  = (const float*)d_in[5];
    const float* bg1  = (const float*)d_in[6];
    const float* Wg2  = (const float*)d_in[7];
    const float* bg2  = (const float*)d_in[8];
    const int*   ridx = (const int*)d_in[9];
    float* out = (float*)d_out;

    __half *xh, *ahp, *bphp, *y1hp, *m2h, *wbt, *wg2t;
    cudaGetSymbolAddress((void**)&xh,    g_xh);
    cudaGetSymbolAddress((void**)&ahp,   g_ah);
    cudaGetSymbolAddress((void**)&bphp,  g_bph);
    cudaGetSymbolAddress((void**)&y1hp,  g_y1h);
    cudaGetSymbolAddress((void**)&m2h,   g_m2h);
    cudaGetSymbolAddress((void**)&wbt,   g_wbt);
    cudaGetSymbolAddress((void**)&wg2t,  g_wg2t);

    const int SMEM_G1 = 3 * (128 * 40 + 64 * 40) * (int)sizeof(__half);  // 46080
    const int SMEM_G3 = 3 * (128 * 40 + 32 * 40) * (int)sizeof(__half);  // 38400
    cudaFuncSetAttribute((const void*)mgemm_kernel<5,128,64>,
                         cudaFuncAttributeMaxDynamicSharedMemorySize, SMEM_G1);
    cudaFuncSetAttribute((const void*)mgemm_kernel<1,128,32>,
                         cudaFuncAttributeMaxDynamicSharedMemorySize, SMEM_G3);

    prep_kernel<<<1152, 256>>>(x, W1, Wg1, Wg2, xh, wbt, wg2t);

    // G1': [a | bp | y1] = x @ [W1a | W1b | Wg1]  -> fp16 outputs
    {
        dim3 grid(3 * Dd / 64, Mrows / 128);     // 24 x 32 = 768 CTAs
        mgemm_kernel<5,128,64><<<grid, 256, SMEM_G1>>>(xh, wbt, b1, nullptr,
                                                       ahp, bphp, y1hp, 3 * Dd, Dd);
    }
    // Fused attention + agg1 + agg2 -> m2 fp16
    attnagg2_kernel<<<Bb * NREG, 256>>>(ahp, bphp, W2, b2, y1hp, xh,
                                        bg1, ridx, m2h);
    // out = leaky(m2 @ Wg2 + bg2): BN=32 -> 8 x 32 = 256 CTAs (full chip)
    {
        dim3 grid(Oo / 32, Mrows / 128);
        mgemm_kernel<1,128,32><<<grid, 256, SMEM_G3>>>(m2h, wg2t, bg2, out,
                                                       nullptr, nullptr, nullptr, Oo, Dd);
    }
}

// round 14
// speedup vs baseline: 1.0350x; 1.0350x over previous
#include <cuda_runtime.h>
#include <cuda_fp16.h>
#include <math.h>

#define Bb 64
#define Cc 64
#define Dd 512
#define Oo 256
#define NREG 8
#define Gg 8
#define Mrows (Bb*Cc)   // 4096

// ---------------- Scratch (device globals) ----------------
__device__ __half g_ah [Mrows*Dd];
__device__ __half g_bph[Mrows*Dd];
__device__ __half g_y1h[Mrows*Dd];
__device__ __half g_xh [Mrows*Dd];
__device__ __half g_m2h[Mrows*Dd];
__device__ __half g_wbt [3*Dd*Dd];
__device__ __half g_wg2t[Oo*Dd];

// ---------------- async / ldmatrix helpers ----------------
__device__ __forceinline__ void cpasync16(void* smem, const void* g)
{
    unsigned sa = (unsigned)__cvta_generic_to_shared(smem);
    asm volatile("cp.async.cg.shared.global [%0], [%1], 16;" :: "r"(sa), "l"(g));
}
__device__ __forceinline__ void cp_commit() { asm volatile("cp.async.commit_group;"); }
template<int N> __device__ __forceinline__ void cp_wait()
{
    asm volatile("cp.async.wait_group %0;" :: "n"(N));
}
__device__ __forceinline__ void ldmx4(unsigned& r0, unsigned& r1, unsigned& r2,
                                      unsigned& r3, const void* p)
{
    unsigned a = (unsigned)__cvta_generic_to_shared(p);
    asm volatile("ldmatrix.sync.aligned.m8n8.x4.shared.b16 {%0,%1,%2,%3}, [%4];"
        : "=r"(r0), "=r"(r1), "=r"(r2), "=r"(r3) : "r"(a));
}
__device__ __forceinline__ void mma_f16(float c[4],
    unsigned a0, unsigned a1, unsigned a2, unsigned a3,
    unsigned b0, unsigned b1)
{
    asm volatile(
        "mma.sync.aligned.m16n8k16.row.col.f32.f16.f16.f32 "
        "{%0,%1,%2,%3}, {%4,%5,%6,%7}, {%8,%9}, {%0,%1,%2,%3};\n"
        : "+f"(c[0]), "+f"(c[1]), "+f"(c[2]), "+f"(c[3])
        : "r"(a0), "r"(a1), "r"(a2), "r"(a3), "r"(b0), "r"(b1));
}
__device__ __forceinline__ unsigned pack_half2(float a, float b)
{
    __half2 h = __halves2half2(__float2half_rn(a), __float2half_rn(b));
    return *(unsigned*)&h;
}

// ---------------- Combined prep kernel ----------------
__device__ __forceinline__ void transpose_tile(
    const float* __restrict__ src, __half* __restrict__ dst,
    int K, int N, int tn, int tk)
{
    __shared__ float tile[32][36];
    const int tid = threadIdx.x;
    const int k0 = tk * 32, n0 = tn * 32;
    {
        int row = tid >> 3, c4 = tid & 7;
        float4 v = *(const float4*)(src + (size_t)(k0 + row) * N + n0 + c4 * 4);
        tile[row][c4 * 4]     = v.x;
        tile[row][c4 * 4 + 1] = v.y;
        tile[row][c4 * 4 + 2] = v.z;
        tile[row][c4 * 4 + 3] = v.w;
    }
    __syncthreads();
    const int nr = tid >> 4;
    const int kp = tid & 15;
    #pragma unroll
    for (int i = 0; i < 2; i++) {
        int n = n0 + nr + 16 * i;
        float v0 = tile[2 * kp    ][nr + 16 * i];
        float v1 = tile[2 * kp + 1][nr + 16 * i];
        *(unsigned*)&dst[(size_t)n * K + k0 + 2 * kp] = pack_half2(v0, v1);
    }
}

__global__ __launch_bounds__(256)
void prep_kernel(const float* __restrict__ x, const float* __restrict__ W1,
                 const float* __restrict__ Wg1, const float* __restrict__ Wg2,
                 __half* __restrict__ xh,
                 __half* __restrict__ wbt, __half* __restrict__ wg2t)
{
    int b = blockIdx.x;
    if (b < 256) {
        transpose_tile(W1, wbt, Dd, Dd, b & 15, b >> 4);
    } else if (b < 512) {
        b -= 256;
        transpose_tile(W1 + (size_t)Dd * Dd, wbt + (size_t)Dd * Dd, Dd, Dd, b & 15, b >> 4);
    } else if (b < 768) {
        b -= 512;
        transpose_tile(Wg1, wbt + 2 * (size_t)Dd * Dd, Dd, Dd, b & 15, b >> 4);
    } else if (b < 896) {
        b -= 768;
        transpose_tile(Wg2, wg2t, Dd, Oo, b & 7, b >> 3);
    } else {
        b -= 896;   // 256 blocks: x -> fp16
        const float4* src = (const float4*)x;
        uint2* dh = (uint2*)xh;
        const int n4 = Mrows * Dd / 4;
        for (int i = b * 256 + threadIdx.x; i < n4; i += 256 * 256) {
            float4 v = src[i];
            dh[i] = make_uint2(pack_half2(v.x, v.y), pack_half2(v.z, v.w));
        }
    }
}

// ---------------- fp16 tensor-core GEMM ----------------
// MODE 1: fp32 out, leaky(z + bias)
// MODE 5: triple fp16 route: col<512 -> Ch raw; 512..1023 -> C2h + bias; >=1024 -> C3h raw
template<int MODE, int BM, int BN, int BK>
__global__ __launch_bounds__(256, 2)
void mgemm_kernel(const __half* __restrict__ A, const __half* __restrict__ Bt,
                  const float* __restrict__ bias,
                  float* __restrict__ C,
                  __half* __restrict__ Ch, __half* __restrict__ C2h,
                  __half* __restrict__ C3h, int N, int K)
{
    constexpr int LDT = BK + 8;
    constexpr int STAGES = 3;
    constexpr int WROWS = BM / 32;
    constexpr int WCOLS = BN * WROWS / 8;
    constexpr int NT = WCOLS / 8;
    constexpr int P  = (WCOLS / 16) ? WCOLS / 16 : 1;
    constexpr int A_SZ = BM * LDT;
    constexpr int B_SZ = BN * LDT;
    constexpr int STG  = A_SZ + B_SZ;
    constexpr int KCH  = BK / 8;                  // 16B chunks per row
    constexpr int ACHUNK = BM * KCH / 256;        // per-thread A chunks
    constexpr int BCHUNK = BN * KCH / 256;        // per-thread B chunks (>=1)
    extern __shared__ __half dsm[];

    const int tid  = threadIdx.x;
    const int wid  = tid >> 5;
    const int lane = tid & 31;
    const int wm   = wid % WROWS;
    const int wn   = wid / WROWS;
    const int row0 = blockIdx.y * BM;
    const int col0 = blockIdx.x * BN;
    const int g = lane >> 2;
    const int t = lane & 3;
    const int lq = lane >> 3, li = lane & 7;
    const int fr_off = (lq & 1) * 8 + li;
    const int fk_off = (lq >> 1) * 8;

    float acc[2][NT][4];
    #pragma unroll
    for (int mt = 0; mt < 2; mt++)
        #pragma unroll
        for (int nt = 0; nt < NT; nt++)
            #pragma unroll
            for (int q = 0; q < 4; q++) acc[mt][nt][q] = 0.f;

    auto load_stage = [&](int st, int kt) {
        __half* sA = dsm + st * STG;
        __half* sB = sA + A_SZ;
        #pragma unroll
        for (int i = 0; i < ACHUNK; i++) {
            int id = tid * ACHUNK + i;
            int r = id / KCH, c = (id % KCH) * 8;
            cpasync16(sA + r * LDT + c, A + (size_t)(row0 + r) * K + kt + c);
        }
        #pragma unroll
        for (int i = 0; i < BCHUNK; i++) {
            int id = tid * BCHUNK + i;
            int r = id / KCH, c = (id % KCH) * 8;
            cpasync16(sB + r * LDT + c, Bt + (size_t)(col0 + r) * K + kt + c);
        }
    };

    const int nk = K / BK;
    load_stage(0, 0); cp_commit();
    load_stage(1, BK); cp_commit();

    for (int s = 0; s < nk; s++) {
        if (s + 2 < nk) { load_stage((s + 2) % STAGES, (s + 2) * BK); cp_commit(); cp_wait<2>(); }
        else if (s + 1 < nk) { cp_wait<1>(); }
        else { cp_wait<0>(); }
        __syncthreads();

        const int st = s % STAGES;
        __half* sA = dsm + st * STG;
        __half* sB = sA + A_SZ;

        #pragma unroll
        for (int kk = 0; kk < BK; kk += 16) {
            unsigned ah[2][4], bv[P][4];
            #pragma unroll
            for (int mt = 0; mt < 2; mt++) {
                const __half* pa = sA + (wm * 32 + mt * 16 + fr_off) * LDT + kk + fk_off;
                ldmx4(ah[mt][0], ah[mt][1], ah[mt][2], ah[mt][3], pa);
            }
            #pragma unroll
            for (int p = 0; p < P; p++) {
                const __half* pb = sB + (wn * WCOLS + p * 16 + fr_off) * LDT + kk + fk_off;
                ldmx4(bv[p][0], bv[p][1], bv[p][2], bv[p][3], pb);
            }
            #pragma unroll
            for (int mt = 0; mt < 2; mt++)
                #pragma unroll
                for (int nt = 0; nt < NT; nt++) {
                    const int p = nt >> 1, o = nt & 1;
                    mma_f16(acc[mt][nt], ah[mt][0], ah[mt][1], ah[mt][2], ah[mt][3],
                            bv[p][o], bv[p][2 + o]);
                }
        }
        __syncthreads();
    }

    #pragma unroll
    for (int mt = 0; mt < 2; mt++) {
        int rbase = row0 + wm * 32 + mt * 16;
        #pragma unroll
        for (int nt = 0; nt < NT; nt++) {
            int cb = col0 + wn * WCOLS + nt * 8 + 2 * t;
            #pragma unroll
            for (int h = 0; h < 2; h++) {
                int r = rbase + g + 8 * h;
                float v0 = acc[mt][nt][2*h];
                float v1 = acc[mt][nt][2*h + 1];
                if (MODE == 5) {
                    if (cb < Dd) {
                        *(unsigned*)&Ch[(size_t)r * Dd + cb] = pack_half2(v0, v1);
                    } else if (cb < 2 * Dd) {
                        int c2 = cb - Dd;
                        v0 += bias[c2]; v1 += bias[c2 + 1];
                        *(unsigned*)&C2h[(size_t)r * Dd + c2] = pack_half2(v0, v1);
                    } else {
                        int c3 = cb - 2 * Dd;
                        *(unsigned*)&C3h[(size_t)r * Dd + c3] = pack_half2(v0, v1);
                    }
                } else {
                    v0 += bias[cb]; v1 += bias[cb + 1];
                    v0 = (v0 >= 0.f) ? v0 : 0.2f * v0;
                    v1 = (v1 >= 0.f) ? v1 : 0.2f * v1;
                    *(float2*)(C + (size_t)r * N + cb) = make_float2(v0, v1);
                }
            }
        }
    }
}

// ---------------------------------------------------------------------------
// Fused attention + both aggregations. y1 and x prefetched via cp.async
// during the score phase (hides their latency under compute).
// ---------------------------------------------------------------------------
__global__ __launch_bounds__(256)
void attnagg2_kernel(const __half* __restrict__ ah, const __half* __restrict__ bph,
                     const float* __restrict__ W2, const float* __restrict__ b2,
                     const __half* __restrict__ y1h, const __half* __restrict__ xh,
                     const float* __restrict__ bg1, const int* __restrict__ ridx,
                     __half* __restrict__ m2h)
{
    __shared__ float  sa[Gg][Dd];      // a (scores), then x1 (phase 2 out)
    __shared__ float  sb[Gg][Dd];      // bp
    __shared__ __half y1s[Gg][Dd];     // prefetched y1 (fp16)
    __shared__ __half xs [Gg][Dd];     // prefetched x  (fp16)
    __shared__ float  sw2[Dd];
    __shared__ float  ssc[Gg][Gg];
    __shared__ float  ww[Gg * Gg];
    __shared__ int    ch[Gg];

    const int tid  = threadIdx.x;
    const int blk  = blockIdx.x;
    const int b    = blk >> 3;
    const int r    = blk & 7;

    if (tid < Gg) ch[tid] = ridx[r * Gg + tid];
    __syncthreads();

    // Prefetch y1 and x (fp16, 8 rows x 64 16B-chunks each = 512 chunks, 2/thread)
    #pragma unroll
    for (int u = 0; u < 2; u++) {
        int id = tid + 256 * u;
        int j = id >> 6, c8 = id & 63;
        size_t roff = (size_t)(b * Cc + ch[j]) * Dd;
        cpasync16(&y1s[j][c8 * 8], y1h + roff + c8 * 8);
        cpasync16(&xs [j][c8 * 8], xh  + roff + c8 * 8);
    }
    cp_commit();

    // Load a/bp and convert to fp32 shared (regular loads)
    #pragma unroll
    for (int u = 0; u < 2; u++) {
        int id = tid + 256 * u;
        int j = id >> 6, c8 = id & 63;
        size_t roff = (size_t)(b * Cc + ch[j]) * Dd;
        uint4 va = ((const uint4*)(ah  + roff))[c8];
        uint4 vb = ((const uint4*)(bph + roff))[c8];
        const unsigned* pa = &va.x;
        const unsigned* pb = &vb.x;
        #pragma unroll
        for (int q = 0; q < 4; q++) {
            float2 fa = __half22float2(*(__half2*)&pa[q]);
            float2 fb = __half22float2(*(__half2*)&pb[q]);
            sa[j][c8 * 8 + 2 * q]     = fa.x;
            sa[j][c8 * 8 + 2 * q + 1] = fa.y;
            sb[j][c8 * 8 + 2 * q]     = fb.x;
            sb[j][c8 * 8 + 2 * q + 1] = fb.y;
        }
    }
    if (tid < 128) ((float4*)sw2)[tid] = ((const float4*)W2)[tid];
    __syncthreads();

    // Scores: warp i vs all 8 columns
    const int wid  = tid >> 5;
    const int lane = tid & 31;
    {
        float accq[Gg];
        #pragma unroll
        for (int q = 0; q < Gg; q++) accq[q] = 0.f;
        for (int t = lane; t < Dd; t += 32) {
            float av = sa[wid][t];
            float wv = sw2[t];
            #pragma unroll
            for (int q = 0; q < Gg; q++) {
                float v = av + sb[q][t];
                v = fmaxf(v, 0.f);
                accq[q] = fmaf(v, wv, accq[q]);
            }
        }
        #pragma unroll
        for (int q = 0; q < Gg; q++) {
            #pragma unroll
            for (int off = 16; off > 0; off >>= 1)
                accq[q] += __shfl_xor_sync(0xffffffffu, accq[q], off);
        }
        if (lane == 0) {
            float bb2 = b2[0];
            #pragma unroll
            for (int q = 0; q < Gg; q++) ssc[wid][q] = accq[q] + bb2;
        }
    }
    __syncthreads();

    // Softmax (exclude diagonal) -> ww
    if (tid < Gg) {
        int i = tid;
        float mx = -1e30f;
        #pragma unroll
        for (int j = 0; j < Gg; j++)
            if (j != i) mx = fmaxf(mx, ssc[i][j]);
        float e[Gg]; float s = 0.f;
        #pragma unroll
        for (int j = 0; j < Gg; j++) {
            e[j] = (j == i) ? 0.f : __expf(ssc[i][j] - mx);
            s += e[j];
        }
        float inv = 1.f / s;
        #pragma unroll
        for (int j = 0; j < Gg; j++) ww[i * Gg + j] = e[j] * inv;
    }
    cp_wait<0>();
    __syncthreads();

    // Phase 2: x1 = 0.5*leaky(adj@y1 + bg1) + 0.5*x  -> sa (fp32)
    #pragma unroll
    for (int u = 0; u < 4; u++) {
        int id = tid + 256 * u;
        int i = id >> 7, d4 = id & 127;
        float wi[Gg];
        #pragma unroll
        for (int j = 0; j < Gg; j++) wi[j] = ww[i * Gg + j];
        float a0 = 0.f, a1 = 0.f, a2 = 0.f, a3 = 0.f;
        #pragma unroll
        for (int j = 0; j < Gg; j++) {
            uint2 yv = *(const uint2*)&y1s[j][d4 * 4];
            float2 y01 = __half22float2(*(__half2*)&yv.x);
            float2 y23 = __half22float2(*(__half2*)&yv.y);
            a0 = fmaf(wi[j], y01.x, a0);
            a1 = fmaf(wi[j], y01.y, a1);
            a2 = fmaf(wi[j], y23.x, a2);
            a3 = fmaf(wi[j], y23.y, a3);
        }
        float4 bv = ((const float4*)bg1)[d4];
        uint2 xv = *(const uint2*)&xs[i][d4 * 4];
        float2 x01 = __half22float2(*(__half2*)&xv.x);
        float2 x23 = __half22float2(*(__half2*)&xv.y);
        float z0 = a0 + bv.x, z1 = a1 + bv.y, z2 = a2 + bv.z, z3 = a3 + bv.w;
        z0 = (z0 >= 0.f) ? z0 : 0.2f * z0;
        z1 = (z1 >= 0.f) ? z1 : 0.2f * z1;
        z2 = (z2 >= 0.f) ? z2 : 0.2f * z2;
        z3 = (z3 >= 0.f) ? z3 : 0.2f * z3;
        sa[i][d4 * 4    ] = 0.5f * z0 + 0.5f * x01.x;
        sa[i][d4 * 4 + 1] = 0.5f * z1 + 0.5f * x01.y;
        sa[i][d4 * 4 + 2] = 0.5f * z2 + 0.5f * x23.x;
        sa[i][d4 * 4 + 3] = 0.5f * z3 + 0.5f * x23.y;
    }
    __syncthreads();

    // Phase 3: m2 = adj @ x1 -> fp16 global
    #pragma unroll
    for (int u = 0; u < 4; u++) {
        int id = tid + 256 * u;
        int i = id >> 7, d4 = id & 127;
        float wi[Gg];
        #pragma unroll
        for (int j = 0; j < Gg; j++) wi[j] = ww[i * Gg + j];
        float a0 = 0.f, a1 = 0.f, a2 = 0.f, a3 = 0.f;
        #pragma unroll
        for (int j = 0; j < Gg; j++) {
            const float* xr = &sa[j][d4 * 4];
            a0 = fmaf(wi[j], xr[0], a0);
            a1 = fmaf(wi[j], xr[1], a1);
            a2 = fmaf(wi[j], xr[2], a2);
            a3 = fmaf(wi[j], xr[3], a3);
        }
        size_t rowoff = (size_t)(b * Cc + ch[i]) * Dd;
        ((uint2*)(m2h + rowoff))[d4] = make_uint2(pack_half2(a0, a1), pack_half2(a2, a3));
    }
}

// ---------------------------------------------------------------------------
extern "C" void kernel_launch(void* const* d_in, const int* in_sizes, int n_in,
                              void* d_out, int out_size)
{
    const float* x    = (const float*)d_in[0];
    const float* W1   = (const float*)d_in[1];
    const float* b1   = (const float*)d_in[2];
    const float* W2   = (const float*)d_in[3];
    const float* b2   = (const float*)d_in[4];
    const float* Wg1  = (const float*)d_in[5];
    const float* bg1  = (const float*)d_in[6];
    const float* Wg2  = (const float*)d_in[7];
    const float* bg2  = (const float*)d_in[8];
    const int*   ridx = (const int*)d_in[9];
    float* out = (float*)d_out;

    __half *xh, *ahp, *bphp, *y1hp, *m2h, *wbt, *wg2t;
    cudaGetSymbolAddress((void**)&xh,    g_xh);
    cudaGetSymbolAddress((void**)&ahp,   g_ah);
    cudaGetSymbolAddress((void**)&bphp,  g_bph);
    cudaGetSymbolAddress((void**)&y1hp,  g_y1h);
    cudaGetSymbolAddress((void**)&m2h,   g_m2h);
    cudaGetSymbolAddress((void**)&wbt,   g_wbt);
    cudaGetSymbolAddress((void**)&wg2t,  g_wg2t);

    const int SMEM_G1 = 3 * (128 * 40 + 64 * 40) * (int)sizeof(__half);  // 46080
    const int SMEM_G3 = 3 * (128 * 72 + 64 * 72) * (int)sizeof(__half);  // 82944
    cudaFuncSetAttribute((const void*)mgemm_kernel<5,128,64,32>,
                         cudaFuncAttributeMaxDynamicSharedMemorySize, SMEM_G1);
    cudaFuncSetAttribute((const void*)mgemm_kernel<1,128,64,64>,
                         cudaFuncAttributeMaxDynamicSharedMemorySize, SMEM_G3);

    prep_kernel<<<1152, 256>>>(x, W1, Wg1, Wg2, xh, wbt, wg2t);

    // G1': [a | bp | y1] = x @ [W1a | W1b | Wg1]  -> fp16 outputs
    {
        dim3 grid(3 * Dd / 64, Mrows / 128);     // 24 x 32 = 768 CTAs
        mgemm_kernel<5,128,64,32><<<grid, 256, SMEM_G1>>>(xh, wbt, b1, nullptr,
                                                          ahp, bphp, y1hp, 3 * Dd, Dd);
    }
    // Fused attention + agg1 + agg2 -> m2 fp16
    attnagg2_kernel<<<Bb * NREG, 256>>>(ahp, bphp, W2, b2, y1hp, xh,
                                        bg1, ridx, m2h);
    // G3: out = leaky(m2 @ Wg2 + bg2), BK=64 (8-stage pipeline)
    {
        dim3 grid(Oo / 64, Mrows / 128);         // 4 x 32 = 128 CTAs
        mgemm_kernel<1,128,64,64><<<grid, 256, SMEM_G3>>>(m2h, wg2t, bg2, out,
                                                          nullptr, nullptr, nullptr, Oo, Dd);
    }
}

// round 15
// speedup vs baseline: 1.0426x; 1.0074x over previous
#include <cuda_runtime.h>
#include <cuda_fp16.h>
#include <math.h>

#define Bb 64
#define Cc 64
#define Dd 512
#define Oo 256
#define NREG 8
#define Gg 8
#define Mrows (Bb*Cc)   // 4096

// ---------------- Scratch (device globals) ----------------
__device__ __half g_ah [Mrows*Dd];
__device__ __half g_bph[Mrows*Dd];
__device__ __half g_y1h[Mrows*Dd];
__device__ __half g_xh [Mrows*Dd];
__device__ __half g_m2h[Mrows*Dd];
__device__ __half g_wbt [3*Dd*Dd];
__device__ __half g_wg2t[Oo*Dd];

// ---------------- async / ldmatrix helpers ----------------
__device__ __forceinline__ void cpasync16(void* smem, const void* g)
{
    unsigned sa = (unsigned)__cvta_generic_to_shared(smem);
    asm volatile("cp.async.cg.shared.global [%0], [%1], 16;" :: "r"(sa), "l"(g));
}
__device__ __forceinline__ void cp_commit() { asm volatile("cp.async.commit_group;"); }
template<int N> __device__ __forceinline__ void cp_wait()
{
    asm volatile("cp.async.wait_group %0;" :: "n"(N));
}
__device__ __forceinline__ void ldmx4(unsigned& r0, unsigned& r1, unsigned& r2,
                                      unsigned& r3, const void* p)
{
    unsigned a = (unsigned)__cvta_generic_to_shared(p);
    asm volatile("ldmatrix.sync.aligned.m8n8.x4.shared.b16 {%0,%1,%2,%3}, [%4];"
        : "=r"(r0), "=r"(r1), "=r"(r2), "=r"(r3) : "r"(a));
}
__device__ __forceinline__ void mma_f16(float c[4],
    unsigned a0, unsigned a1, unsigned a2, unsigned a3,
    unsigned b0, unsigned b1)
{
    asm volatile(
        "mma.sync.aligned.m16n8k16.row.col.f32.f16.f16.f32 "
        "{%0,%1,%2,%3}, {%4,%5,%6,%7}, {%8,%9}, {%0,%1,%2,%3};\n"
        : "+f"(c[0]), "+f"(c[1]), "+f"(c[2]), "+f"(c[3])
        : "r"(a0), "r"(a1), "r"(a2), "r"(a3), "r"(b0), "r"(b1));
}
__device__ __forceinline__ unsigned pack_half2(float a, float b)
{
    __half2 h = __halves2half2(__float2half_rn(a), __float2half_rn(b));
    return *(unsigned*)&h;
}

// ---------------- Combined prep kernel ----------------
__device__ __forceinline__ void transpose_tile(
    const float* __restrict__ src, __half* __restrict__ dst,
    int K, int N, int tn, int tk)
{
    __shared__ float tile[32][36];
    const int tid = threadIdx.x;
    const int k0 = tk * 32, n0 = tn * 32;
    {
        int row = tid >> 3, c4 = tid & 7;
        float4 v = *(const float4*)(src + (size_t)(k0 + row) * N + n0 + c4 * 4);
        tile[row][c4 * 4]     = v.x;
        tile[row][c4 * 4 + 1] = v.y;
        tile[row][c4 * 4 + 2] = v.z;
        tile[row][c4 * 4 + 3] = v.w;
    }
    __syncthreads();
    const int nr = tid >> 4;
    const int kp = tid & 15;
    #pragma unroll
    for (int i = 0; i < 2; i++) {
        int n = n0 + nr + 16 * i;
        float v0 = tile[2 * kp    ][nr + 16 * i];
        float v1 = tile[2 * kp + 1][nr + 16 * i];
        *(unsigned*)&dst[(size_t)n * K + k0 + 2 * kp] = pack_half2(v0, v1);
    }
}

__global__ __launch_bounds__(256)
void prep_kernel(const float* __restrict__ x, const float* __restrict__ W1,
                 const float* __restrict__ Wg1, const float* __restrict__ Wg2,
                 __half* __restrict__ xh,
                 __half* __restrict__ wbt, __half* __restrict__ wg2t)
{
    int b = blockIdx.x;
    if (b < 256) {
        transpose_tile(W1, wbt, Dd, Dd, b & 15, b >> 4);
    } else if (b < 512) {
        b -= 256;
        transpose_tile(W1 + (size_t)Dd * Dd, wbt + (size_t)Dd * Dd, Dd, Dd, b & 15, b >> 4);
    } else if (b < 768) {
        b -= 512;
        transpose_tile(Wg1, wbt + 2 * (size_t)Dd * Dd, Dd, Dd, b & 15, b >> 4);
    } else if (b < 896) {
        b -= 768;
        transpose_tile(Wg2, wg2t, Dd, Oo, b & 7, b >> 3);
    } else {
        b -= 896;   // 256 blocks: x -> fp16
        const float4* src = (const float4*)x;
        uint2* dh = (uint2*)xh;
        const int n4 = Mrows * Dd / 4;
        for (int i = b * 256 + threadIdx.x; i < n4; i += 256 * 256) {
            float4 v = src[i];
            dh[i] = make_uint2(pack_half2(v.x, v.y), pack_half2(v.z, v.w));
        }
    }
}

// ---------------- fp16 tensor-core GEMM ----------------
// MODE 1: fp32 out, leaky(z + bias)
// MODE 5: triple fp16 route: col<512 -> Ch raw; 512..1023 -> C2h + bias; >=1024 -> C3h raw
template<int MODE, int BM, int BN, int BK>
__global__ __launch_bounds__(256, 2)
void mgemm_kernel(const __half* __restrict__ A, const __half* __restrict__ Bt,
                  const float* __restrict__ bias,
                  float* __restrict__ C,
                  __half* __restrict__ Ch, __half* __restrict__ C2h,
                  __half* __restrict__ C3h, int N, int K)
{
    constexpr int LDT = BK + 8;
    constexpr int STAGES = 3;
    constexpr int WROWS = BM / 32;
    constexpr int WCOLS = BN * WROWS / 8;
    constexpr int NT = WCOLS / 8;
    constexpr int P  = (WCOLS / 16) ? WCOLS / 16 : 1;
    constexpr int A_SZ = BM * LDT;
    constexpr int B_SZ = BN * LDT;
    constexpr int STG  = A_SZ + B_SZ;
    constexpr int KCH  = BK / 8;
    constexpr int ACHUNK = BM * KCH / 256;
    constexpr int BCHUNK = BN * KCH / 256;
    extern __shared__ __half dsm[];

    const int tid  = threadIdx.x;
    const int wid  = tid >> 5;
    const int lane = tid & 31;
    const int wm   = wid % WROWS;
    const int wn   = wid / WROWS;
    const int row0 = blockIdx.y * BM;
    const int col0 = blockIdx.x * BN;
    const int g = lane >> 2;
    const int t = lane & 3;
    const int lq = lane >> 3, li = lane & 7;
    const int fr_off = (lq & 1) * 8 + li;
    const int fk_off = (lq >> 1) * 8;

    float acc[2][NT][4];
    #pragma unroll
    for (int mt = 0; mt < 2; mt++)
        #pragma unroll
        for (int nt = 0; nt < NT; nt++)
            #pragma unroll
            for (int q = 0; q < 4; q++) acc[mt][nt][q] = 0.f;

    auto load_stage = [&](int st, int kt) {
        __half* sA = dsm + st * STG;
        __half* sB = sA + A_SZ;
        #pragma unroll
        for (int i = 0; i < ACHUNK; i++) {
            int id = tid * ACHUNK + i;
            int r = id / KCH, c = (id % KCH) * 8;
            cpasync16(sA + r * LDT + c, A + (size_t)(row0 + r) * K + kt + c);
        }
        #pragma unroll
        for (int i = 0; i < BCHUNK; i++) {
            int id = tid * BCHUNK + i;
            int r = id / KCH, c = (id % KCH) * 8;
            cpasync16(sB + r * LDT + c, Bt + (size_t)(col0 + r) * K + kt + c);
        }
    };

    const int nk = K / BK;
    load_stage(0, 0); cp_commit();
    load_stage(1, BK); cp_commit();

    for (int s = 0; s < nk; s++) {
        if (s + 2 < nk) { load_stage((s + 2) % STAGES, (s + 2) * BK); cp_commit(); cp_wait<2>(); }
        else if (s + 1 < nk) { cp_wait<1>(); }
        else { cp_wait<0>(); }
        __syncthreads();

        const int st = s % STAGES;
        __half* sA = dsm + st * STG;
        __half* sB = sA + A_SZ;

        #pragma unroll
        for (int kk = 0; kk < BK; kk += 16) {
            unsigned ah[2][4], bv[P][4];
            #pragma unroll
            for (int mt = 0; mt < 2; mt++) {
                const __half* pa = sA + (wm * 32 + mt * 16 + fr_off) * LDT + kk + fk_off;
                ldmx4(ah[mt][0], ah[mt][1], ah[mt][2], ah[mt][3], pa);
            }
            #pragma unroll
            for (int p = 0; p < P; p++) {
                const __half* pb = sB + (wn * WCOLS + p * 16 + fr_off) * LDT + kk + fk_off;
                ldmx4(bv[p][0], bv[p][1], bv[p][2], bv[p][3], pb);
            }
            #pragma unroll
            for (int mt = 0; mt < 2; mt++)
                #pragma unroll
                for (int nt = 0; nt < NT; nt++) {
                    const int p = nt >> 1, o = nt & 1;
                    mma_f16(acc[mt][nt], ah[mt][0], ah[mt][1], ah[mt][2], ah[mt][3],
                            bv[p][o], bv[p][2 + o]);
                }
        }
        __syncthreads();
    }

    #pragma unroll
    for (int mt = 0; mt < 2; mt++) {
        int rbase = row0 + wm * 32 + mt * 16;
        #pragma unroll
        for (int nt = 0; nt < NT; nt++) {
            int cb = col0 + wn * WCOLS + nt * 8 + 2 * t;
            #pragma unroll
            for (int h = 0; h < 2; h++) {
                int r = rbase + g + 8 * h;
                float v0 = acc[mt][nt][2*h];
                float v1 = acc[mt][nt][2*h + 1];
                if (MODE == 5) {
                    if (cb < Dd) {
                        *(unsigned*)&Ch[(size_t)r * Dd + cb] = pack_half2(v0, v1);
                    } else if (cb < 2 * Dd) {
                        int c2 = cb - Dd;
                        v0 += bias[c2]; v1 += bias[c2 + 1];
                        *(unsigned*)&C2h[(size_t)r * Dd + c2] = pack_half2(v0, v1);
                    } else {
                        int c3 = cb - 2 * Dd;
                        *(unsigned*)&C3h[(size_t)r * Dd + c3] = pack_half2(v0, v1);
                    }
                } else {
                    v0 += bias[cb]; v1 += bias[cb + 1];
                    v0 = (v0 >= 0.f) ? v0 : 0.2f * v0;
                    v1 = (v1 >= 0.f) ? v1 : 0.2f * v1;
                    *(float2*)(C + (size_t)r * N + cb) = make_float2(v0, v1);
                }
            }
        }
    }
}

// ---------------------------------------------------------------------------
// Fused attention + both aggregations (R14 version, unchanged)
// ---------------------------------------------------------------------------
__global__ __launch_bounds__(256)
void attnagg2_kernel(const __half* __restrict__ ah, const __half* __restrict__ bph,
                     const float* __restrict__ W2, const float* __restrict__ b2,
                     const __half* __restrict__ y1h, const __half* __restrict__ xh,
                     const float* __restrict__ bg1, const int* __restrict__ ridx,
                     __half* __restrict__ m2h)
{
    __shared__ float  sa[Gg][Dd];
    __shared__ float  sb[Gg][Dd];
    __shared__ __half y1s[Gg][Dd];
    __shared__ __half xs [Gg][Dd];
    __shared__ float  sw2[Dd];
    __shared__ float  ssc[Gg][Gg];
    __shared__ float  ww[Gg * Gg];
    __shared__ int    ch[Gg];

    const int tid  = threadIdx.x;
    const int blk  = blockIdx.x;
    const int b    = blk >> 3;
    const int r    = blk & 7;

    if (tid < Gg) ch[tid] = ridx[r * Gg + tid];
    __syncthreads();

    #pragma unroll
    for (int u = 0; u < 2; u++) {
        int id = tid + 256 * u;
        int j = id >> 6, c8 = id & 63;
        size_t roff = (size_t)(b * Cc + ch[j]) * Dd;
        cpasync16(&y1s[j][c8 * 8], y1h + roff + c8 * 8);
        cpasync16(&xs [j][c8 * 8], xh  + roff + c8 * 8);
    }
    cp_commit();

    #pragma unroll
    for (int u = 0; u < 2; u++) {
        int id = tid + 256 * u;
        int j = id >> 6, c8 = id & 63;
        size_t roff = (size_t)(b * Cc + ch[j]) * Dd;
        uint4 va = ((const uint4*)(ah  + roff))[c8];
        uint4 vb = ((const uint4*)(bph + roff))[c8];
        const unsigned* pa = &va.x;
        const unsigned* pb = &vb.x;
        #pragma unroll
        for (int q = 0; q < 4; q++) {
            float2 fa = __half22float2(*(__half2*)&pa[q]);
            float2 fb = __half22float2(*(__half2*)&pb[q]);
            sa[j][c8 * 8 + 2 * q]     = fa.x;
            sa[j][c8 * 8 + 2 * q + 1] = fa.y;
            sb[j][c8 * 8 + 2 * q]     = fb.x;
            sb[j][c8 * 8 + 2 * q + 1] = fb.y;
        }
    }
    if (tid < 128) ((float4*)sw2)[tid] = ((const float4*)W2)[tid];
    __syncthreads();

    const int wid  = tid >> 5;
    const int lane = tid & 31;
    {
        float accq[Gg];
        #pragma unroll
        for (int q = 0; q < Gg; q++) accq[q] = 0.f;
        for (int t = lane; t < Dd; t += 32) {
            float av = sa[wid][t];
            float wv = sw2[t];
            #pragma unroll
            for (int q = 0; q < Gg; q++) {
                float v = av + sb[q][t];
                v = fmaxf(v, 0.f);
                accq[q] = fmaf(v, wv, accq[q]);
            }
        }
        #pragma unroll
        for (int q = 0; q < Gg; q++) {
            #pragma unroll
            for (int off = 16; off > 0; off >>= 1)
                accq[q] += __shfl_xor_sync(0xffffffffu, accq[q], off);
        }
        if (lane == 0) {
            float bb2 = b2[0];
            #pragma unroll
            for (int q = 0; q < Gg; q++) ssc[wid][q] = accq[q] + bb2;
        }
    }
    __syncthreads();

    if (tid < Gg) {
        int i = tid;
        float mx = -1e30f;
        #pragma unroll
        for (int j = 0; j < Gg; j++)
            if (j != i) mx = fmaxf(mx, ssc[i][j]);
        float e[Gg]; float s = 0.f;
        #pragma unroll
        for (int j = 0; j < Gg; j++) {
            e[j] = (j == i) ? 0.f : __expf(ssc[i][j] - mx);
            s += e[j];
        }
        float inv = 1.f / s;
        #pragma unroll
        for (int j = 0; j < Gg; j++) ww[i * Gg + j] = e[j] * inv;
    }
    cp_wait<0>();
    __syncthreads();

    #pragma unroll
    for (int u = 0; u < 4; u++) {
        int id = tid + 256 * u;
        int i = id >> 7, d4 = id & 127;
        float wi[Gg];
        #pragma unroll
        for (int j = 0; j < Gg; j++) wi[j] = ww[i * Gg + j];
        float a0 = 0.f, a1 = 0.f, a2 = 0.f, a3 = 0.f;
        #pragma unroll
        for (int j = 0; j < Gg; j++) {
            uint2 yv = *(const uint2*)&y1s[j][d4 * 4];
            float2 y01 = __half22float2(*(__half2*)&yv.x);
            float2 y23 = __half22float2(*(__half2*)&yv.y);
            a0 = fmaf(wi[j], y01.x, a0);
            a1 = fmaf(wi[j], y01.y, a1);
            a2 = fmaf(wi[j], y23.x, a2);
            a3 = fmaf(wi[j], y23.y, a3);
        }
        float4 bv = ((const float4*)bg1)[d4];
        uint2 xv = *(const uint2*)&xs[i][d4 * 4];
        float2 x01 = __half22float2(*(__half2*)&xv.x);
        float2 x23 = __half22float2(*(__half2*)&xv.y);
        float z0 = a0 + bv.x, z1 = a1 + bv.y, z2 = a2 + bv.z, z3 = a3 + bv.w;
        z0 = (z0 >= 0.f) ? z0 : 0.2f * z0;
        z1 = (z1 >= 0.f) ? z1 : 0.2f * z1;
        z2 = (z2 >= 0.f) ? z2 : 0.2f * z2;
        z3 = (z3 >= 0.f) ? z3 : 0.2f * z3;
        sa[i][d4 * 4    ] = 0.5f * z0 + 0.5f * x01.x;
        sa[i][d4 * 4 + 1] = 0.5f * z1 + 0.5f * x01.y;
        sa[i][d4 * 4 + 2] = 0.5f * z2 + 0.5f * x23.x;
        sa[i][d4 * 4 + 3] = 0.5f * z3 + 0.5f * x23.y;
    }
    __syncthreads();

    #pragma unroll
    for (int u = 0; u < 4; u++) {
        int id = tid + 256 * u;
        int i = id >> 7, d4 = id & 127;
        float wi[Gg];
        #pragma unroll
        for (int j = 0; j < Gg; j++) wi[j] = ww[i * Gg + j];
        float a0 = 0.f, a1 = 0.f, a2 = 0.f, a3 = 0.f;
        #pragma unroll
        for (int j = 0; j < Gg; j++) {
            const float* xr = &sa[j][d4 * 4];
            a0 = fmaf(wi[j], xr[0], a0);
            a1 = fmaf(wi[j], xr[1], a1);
            a2 = fmaf(wi[j], xr[2], a2);
            a3 = fmaf(wi[j], xr[3], a3);
        }
        size_t rowoff = (size_t)(b * Cc + ch[i]) * Dd;
        ((uint2*)(m2h + rowoff))[d4] = make_uint2(pack_half2(a0, a1), pack_half2(a2, a3));
    }
}

// ---------------------------------------------------------------------------
extern "C" void kernel_launch(void* const* d_in, const int* in_sizes, int n_in,
                              void* d_out, int out_size)
{
    const float* x    = (const float*)d_in[0];
    const float* W1   = (const float*)d_in[1];
    const float* b1   = (const float*)d_in[2];
    const float* W2   = (const float*)d_in[3];
    const float* b2   = (const float*)d_in[4];
    const float* Wg1  = (const float*)d_in[5];
    const float* bg1  = (const float*)d_in[6];
    const float* Wg2  = (const float*)d_in[7];
    const float* bg2  = (const float*)d_in[8];
    const int*   ridx = (const int*)d_in[9];
    float* out = (float*)d_out;

    __half *xh, *ahp, *bphp, *y1hp, *m2h, *wbt, *wg2t;
    cudaGetSymbolAddress((void**)&xh,    g_xh);
    cudaGetSymbolAddress((void**)&ahp,   g_ah);
    cudaGetSymbolAddress((void**)&bphp,  g_bph);
    cudaGetSymbolAddress((void**)&y1hp,  g_y1h);
    cudaGetSymbolAddress((void**)&m2h,   g_m2h);
    cudaGetSymbolAddress((void**)&wbt,   g_wbt);
    cudaGetSymbolAddress((void**)&wg2t,  g_wg2t);

    const int SMEM_G1 = 3 * (128 * 40 + 64 * 40) * (int)sizeof(__half);  // 46080
    const int SMEM_G3 = 3 * (64 * 72 + 64 * 72) * (int)sizeof(__half);   // 55296
    cudaFuncSetAttribute((const void*)mgemm_kernel<5,128,64,32>,
                         cudaFuncAttributeMaxDynamicSharedMemorySize, SMEM_G1);
    cudaFuncSetAttribute((const void*)mgemm_kernel<1,64,64,64>,
                         cudaFuncAttributeMaxDynamicSharedMemorySize, SMEM_G3);

    prep_kernel<<<1152, 256>>>(x, W1, Wg1, Wg2, xh, wbt, wg2t);

    // G1': [a | bp | y1] = x @ [W1a | W1b | Wg1]  -> fp16 outputs
    {
        dim3 grid(3 * Dd / 64, Mrows / 128);     // 24 x 32 = 768 CTAs
        mgemm_kernel<5,128,64,32><<<grid, 256, SMEM_G1>>>(xh, wbt, b1, nullptr,
                                                          ahp, bphp, y1hp, 3 * Dd, Dd);
    }
    // Fused attention + agg1 + agg2 -> m2 fp16
    attnagg2_kernel<<<Bb * NREG, 256>>>(ahp, bphp, W2, b2, y1hp, xh,
                                        bg1, ridx, m2h);
    // G3: out = leaky(m2 @ Wg2 + bg2), BM=64/BK=64 -> 256 CTAs, 2 CTA/SM
    {
        dim3 grid(Oo / 64, Mrows / 64);          // 4 x 64 = 256 CTAs
        mgemm_kernel<1,64,64,64><<<grid, 256, SMEM_G3>>>(m2h, wg2t, bg2, out,
                                                         nullptr, nullptr, nullptr, Oo, Dd);
    }
}